// round 10
// baseline (speedup 1.0000x reference)
#include <cuda_runtime.h>
#include <cuda_bf16.h>
#include <cstdint>
#include <math.h>

#define LD 68

// ---------------- scratch ----------------
__device__ float g_q[2048 * 2048];
__device__ float g_k[2048 * 512];
__device__ float g_v[2048 * 512];
__device__ float g_ql[2 * 32 * 1024 * 64];
__device__ float g_kl[2 * 8 * 1024 * 64];
__device__ float g_gl[2 * 8 * 1024 * 64];
__device__ float g_vh[2 * 8 * 1024 * 64];
__device__ float g_uw[2 * 8 * 16 * 64 * 128];
__device__ float g_up[2 * 8 * 16 * 64 * 64];
__device__ float g_Spre[2 * 8 * 16 * 64 * 64];
__device__ float g_olin[2048 * 2048];
__device__ float g_lsum[2 * 32 * 1024];

__device__ __nv_bfloat16 g_Ah[2048 * 2048];
__device__ __nv_bfloat16 g_Al[2048 * 2048];
__device__ __nv_bfloat16 g_Wqh[2048 * 2048];
__device__ __nv_bfloat16 g_Wql[2048 * 2048];
__device__ __nv_bfloat16 g_Wkh[512 * 2048];
__device__ __nv_bfloat16 g_Wkl[512 * 2048];
__device__ __nv_bfloat16 g_Wvh[512 * 2048];
__device__ __nv_bfloat16 g_Wvl[512 * 2048];
__device__ __nv_bfloat16 g_Woh[2048 * 2048];
__device__ __nv_bfloat16 g_Wol[2048 * 2048];

// bf16 split q/k/v for HMMA attention (head-major)
__device__ __nv_bfloat16 g_qsh[2 * 32 * 1024 * 64];
__device__ __nv_bfloat16 g_qsl[2 * 32 * 1024 * 64];
__device__ __nv_bfloat16 g_ksh[2 * 8 * 1024 * 64];
__device__ __nv_bfloat16 g_ksl[2 * 8 * 1024 * 64];
__device__ __nv_bfloat16 g_vsh[2 * 8 * 1024 * 64];
__device__ __nv_bfloat16 g_vsl[2 * 8 * 1024 * 64];

__device__ __forceinline__ uint32_t smem_u32(const void* p) {
  uint32_t a;
  asm("{ .reg .u64 t; cvta.to.shared.u64 t, %1; cvt.u32.u64 %0, t; }" : "=r"(a) : "l"(p));
  return a;
}

#define LDSM4(r, addr)                                                        \
  asm volatile("ldmatrix.sync.aligned.m8n8.x4.shared.b16 {%0,%1,%2,%3}, [%4];"\
               : "=r"((r)[0]), "=r"((r)[1]), "=r"((r)[2]), "=r"((r)[3])       \
               : "r"(addr))

#define LDSM4T(r, addr)                                                       \
  asm volatile(                                                               \
      "ldmatrix.sync.aligned.m8n8.x4.trans.shared.b16 {%0,%1,%2,%3}, [%4];"   \
      : "=r"((r)[0]), "=r"((r)[1]), "=r"((r)[2]), "=r"((r)[3])                \
      : "r"(addr))

#define MMA16816(c, a, b)                                                     \
  asm volatile(                                                               \
      "mma.sync.aligned.m16n8k16.row.col.f32.bf16.bf16.f32 "                  \
      "{%0,%1,%2,%3},{%4,%5,%6,%7},{%8,%9},{%0,%1,%2,%3};"                    \
      : "+f"((c)[0]), "+f"((c)[1]), "+f"((c)[2]), "+f"((c)[3])                \
      : "r"((a)[0]), "r"((a)[1]), "r"((a)[2]), "r"((a)[3]),                   \
        "r"((b)[0]), "r"((b)[1]))

#define CPA16(dst, src)                                                       \
  asm volatile("cp.async.cg.shared.global [%0], [%1], 16;" :: "r"(dst), "l"(src))
#define CPCOMMIT() asm volatile("cp.async.commit_group;")

// ---------------- split kernels ----------------
__global__ __launch_bounds__(256) void split_kernel(
    const float* __restrict__ x, __nv_bfloat16* __restrict__ hi,
    __nv_bfloat16* __restrict__ lo, int n4) {
  int i = blockIdx.x * 256 + threadIdx.x;
  if (i >= n4) return;
  float4 v = ((const float4*)x)[i];
  __nv_bfloat16 h0 = __float2bfloat16(v.x), h1 = __float2bfloat16(v.y);
  __nv_bfloat16 h2 = __float2bfloat16(v.z), h3 = __float2bfloat16(v.w);
  __nv_bfloat16 l0 = __float2bfloat16(v.x - __bfloat162float(h0));
  __nv_bfloat16 l1 = __float2bfloat16(v.y - __bfloat162float(h1));
  __nv_bfloat16 l2 = __float2bfloat16(v.z - __bfloat162float(h2));
  __nv_bfloat16 l3 = __float2bfloat16(v.w - __bfloat162float(h3));
  __nv_bfloat162* H = (__nv_bfloat162*)hi;
  __nv_bfloat162* L = (__nv_bfloat162*)lo;
  H[2 * i] = __halves2bfloat162(h0, h1);
  H[2 * i + 1] = __halves2bfloat162(h2, h3);
  L[2 * i] = __halves2bfloat162(l0, l1);
  L[2 * i + 1] = __halves2bfloat162(l2, l3);
}

__global__ __launch_bounds__(256) void splitT_kernel(
    const float* __restrict__ W, __nv_bfloat16* __restrict__ hiT,
    __nv_bfloat16* __restrict__ loT, int K, int N) {
  __shared__ float t[32][33];
  int nx = blockIdx.x * 32, ky = blockIdx.y * 32;
  int tx = threadIdx.x & 31, ty = threadIdx.x >> 5;
  for (int j = ty; j < 32; j += 8)
    t[j][tx] = W[(size_t)(ky + j) * N + nx + tx];
  __syncthreads();
  for (int j = ty; j < 32; j += 8) {
    float v = t[tx][j];
    __nv_bfloat16 h = __float2bfloat16(v);
    __nv_bfloat16 l = __float2bfloat16(v - __bfloat162float(h));
    size_t o = (size_t)(nx + j) * K + ky + tx;
    hiT[o] = h;
    loT[o] = l;
  }
}

// ---------------- HMMA bf16 split GEMM ----------------
__global__ __launch_bounds__(256) void hmma_gemm(
    const __nv_bfloat16* __restrict__ Ah, const __nv_bfloat16* __restrict__ Al,
    const __nv_bfloat16* __restrict__ Bh, const __nv_bfloat16* __restrict__ Bl,
    float* __restrict__ C, int N, int K) {
  extern __shared__ __align__(128) char smem[];
  const uint32_t sb = smem_u32(smem);
  const int tid = threadIdx.x, wid = tid >> 5, lane = tid & 31;
  const int wy = wid & 3, wx = wid >> 2;
  const int m0 = blockIdx.y * 128, n0 = blockIdx.x * 128;
  const int nchunks = K >> 5;
  const __nv_bfloat16* srcs[4] = {Ah, Al, Bh, Bl};

  float acc[2][8][4];
#pragma unroll
  for (int mt = 0; mt < 2; mt++)
#pragma unroll
    for (int nt = 0; nt < 8; nt++)
#pragma unroll
      for (int e = 0; e < 4; e++) acc[mt][nt][e] = 0.f;

#pragma unroll
  for (int pc = 0; pc < 2; pc++) {
    uint32_t base = sb + pc * 40960;
#pragma unroll
    for (int it = 0; it < 8; it++) {
      int idx = it * 256 + tid;
      int mat = idx >> 9;
      int r = (idx >> 2) & 127;
      int seg = idx & 3;
      int grow = (mat < 2 ? m0 : n0) + r;
      const char* g = (const char*)(srcs[mat] + (size_t)grow * K + pc * 32) + seg * 16;
      CPA16(base + mat * 10240 + r * 80 + seg * 16, g);
    }
    CPCOMMIT();
  }

  for (int kc = 0; kc < nchunks; kc++) {
    if (kc == nchunks - 1)
      asm volatile("cp.async.wait_group 0;");
    else
      asm volatile("cp.async.wait_group 1;");
    __syncthreads();
    const uint32_t base = sb + (kc & 1) * 40960;
#pragma unroll
    for (int ks = 0; ks < 2; ks++) {
      uint32_t ah[2][4], al[2][4], bh[8][2], bl[8][2];
#pragma unroll
      for (int mt = 0; mt < 2; mt++) {
        int row = wy * 32 + mt * 16 + (lane & 15);
        uint32_t off = row * 80 + (ks * 16 + (lane >> 4) * 8) * 2;
        LDSM4(ah[mt], base + off);
        LDSM4(al[mt], base + 10240 + off);
      }
#pragma unroll
      for (int np = 0; np < 4; np++) {
        int j = lane >> 3;
        int row = wx * 64 + np * 16 + (j >> 1) * 8 + (lane & 7);
        uint32_t off = row * 80 + (ks * 16 + (j & 1) * 8) * 2;
        LDSM4(bh[2 * np], base + 20480 + off);
        LDSM4(bl[2 * np], base + 30720 + off);
      }
#pragma unroll
      for (int mt = 0; mt < 2; mt++)
#pragma unroll
        for (int nt = 0; nt < 8; nt++) {
          MMA16816(acc[mt][nt], ah[mt], bh[nt]);
          MMA16816(acc[mt][nt], ah[mt], bl[nt]);
          MMA16816(acc[mt][nt], al[mt], bh[nt]);
        }
    }
    __syncthreads();
    if (kc + 2 < nchunks) {
      uint32_t lbase = sb + (kc & 1) * 40960;
#pragma unroll
      for (int it = 0; it < 8; it++) {
        int idx = it * 256 + tid;
        int mat = idx >> 9;
        int r = (idx >> 2) & 127;
        int seg = idx & 3;
        int grow = (mat < 2 ? m0 : n0) + r;
        const char* g =
            (const char*)(srcs[mat] + (size_t)grow * K + (kc + 2) * 32) + seg * 16;
        CPA16(lbase + mat * 10240 + r * 80 + seg * 16, g);
      }
      CPCOMMIT();
    }
  }

#pragma unroll
  for (int mt = 0; mt < 2; mt++)
#pragma unroll
    for (int nt = 0; nt < 8; nt++) {
      int row = m0 + wy * 32 + mt * 16 + (lane >> 2);
      int col = n0 + wx * 64 + nt * 8 + (lane & 3) * 2;
      *(float2*)&C[(size_t)row * N + col] =
          make_float2(acc[mt][nt][0], acc[mt][nt][1]);
      *(float2*)&C[(size_t)(row + 8) * N + col] =
          make_float2(acc[mt][nt][2], acc[mt][nt][3]);
    }
}

// ---------------- feature maps + bf16 splits ----------------
__global__ __launch_bounds__(256) void prep_kernel() {
  int gw = (blockIdx.x * 256 + threadIdx.x) >> 5;
  int lane = threadIdx.x & 31;
  if (gw < 65536) {
    int token = gw >> 5, h = gw & 31;
    const float* src = g_q + (size_t)token * 2048 + h * 64;
    float x0 = src[lane], x1 = src[lane + 32];
    float mx = fmaxf(x0, x1);
#pragma unroll
    for (int o = 16; o > 0; o >>= 1) mx = fmaxf(mx, __shfl_xor_sync(0xffffffffu, mx, o));
    float e0 = __expf(x0 - mx), e1 = __expf(x1 - mx);
    float s = e0 + e1;
#pragma unroll
    for (int o = 16; o > 0; o >>= 1) s += __shfl_xor_sync(0xffffffffu, s, o);
    float inv = 1.f / s;
    int b = token >> 10, n = token & 1023;
    size_t hb = ((size_t)((b * 32 + h) * 1024 + n)) * 64;
    g_ql[hb + lane] = e0 * inv;
    g_ql[hb + lane + 32] = e1 * inv;
    float s0 = x0 * 0.125f, s1 = x1 * 0.125f;
    __nv_bfloat16 h0 = __float2bfloat16(s0), h1 = __float2bfloat16(s1);
    g_qsh[hb + lane] = h0;
    g_qsh[hb + lane + 32] = h1;
    g_qsl[hb + lane] = __float2bfloat16(s0 - __bfloat162float(h0));
    g_qsl[hb + lane + 32] = __float2bfloat16(s1 - __bfloat162float(h1));
  } else {
    int j = gw - 65536;
    int token = j >> 3, hk = j & 7;
    const float* ks = g_k + (size_t)token * 512 + hk * 64;
    const float* vs = g_v + (size_t)token * 512 + hk * 64;
    float x0 = ks[lane], x1 = ks[lane + 32];
    float v0 = vs[lane], v1 = vs[lane + 32];
    float mx = fmaxf(x0, x1);
#pragma unroll
    for (int o = 16; o > 0; o >>= 1) mx = fmaxf(mx, __shfl_xor_sync(0xffffffffu, mx, o));
    float e0 = __expf(x0 - mx), e1 = __expf(x1 - mx);
    float s = e0 + e1;
#pragma unroll
    for (int o = 16; o > 0; o >>= 1) s += __shfl_xor_sync(0xffffffffu, s, o);
    float inv = 1.f / s;
    int b = token >> 10, n = token & 1023;
    size_t base = ((size_t)((b * 8 + hk) * 1024 + n)) * 64;
    g_kl[base + lane] = e0 * inv;
    g_kl[base + lane + 32] = e1 * inv;
    g_gl[base + lane] = (fminf(x0, 0.f) - log1pf(__expf(-fabsf(x0)))) * 0.0625f;
    g_gl[base + lane + 32] = (fminf(x1, 0.f) - log1pf(__expf(-fabsf(x1)))) * 0.0625f;
    g_vh[base + lane] = v0;
    g_vh[base + lane + 32] = v1;
    __nv_bfloat16 kh0 = __float2bfloat16(x0), kh1 = __float2bfloat16(x1);
    g_ksh[base + lane] = kh0;
    g_ksh[base + lane + 32] = kh1;
    g_ksl[base + lane] = __float2bfloat16(x0 - __bfloat162float(kh0));
    g_ksl[base + lane + 32] = __float2bfloat16(x1 - __bfloat162float(kh1));
    __nv_bfloat16 vh0 = __float2bfloat16(v0), vh1 = __float2bfloat16(v1);
    g_vsh[base + lane] = vh0;
    g_vsh[base + lane + 32] = vh1;
    g_vsl[base + lane] = __float2bfloat16(v0 - __bfloat162float(vh0));
    g_vsl[base + lane + 32] = __float2bfloat16(v1 - __bfloat162float(vh1));
  }
}

// ---------------- per-chunk u,w ----------------
__global__ __launch_bounds__(256) void uw_kernel() {
  extern __shared__ float sm_uw[];
  float* kcT = sm_uw;
  float* kb = kcT + 64 * LD;
  float* L = kb + 64 * LD;
  float* uw = L + 64 * LD;
  const int bx = blockIdx.x;
  const int g = bx >> 4, ch = bx & 15;
  const int tid = threadIdx.x, tx = tid & 15, ty = tid >> 4;
  size_t base = ((size_t)g * 1024 + ch * 64) * 64;
  for (int idx = tid; idx < 4096; idx += 256) {
    int r = idx >> 6, c = idx & 63;
    float kv = g_kl[base + idx];
    float gv = g_gl[base + idx];
    float vv = g_vh[base + idx];
    kcT[c * LD + r] = kv;
    float kbv = kv * gv;
    kb[r * LD + c] = kbv;
    uw[r * 136 + c] = vv * gv;
    uw[r * 136 + 64 + c] = kbv;
  }
  __syncthreads();
  float acc[4][4] = {};
#pragma unroll 8
  for (int d = 0; d < 64; d++) {
    float a[4];
#pragma unroll
    for (int i = 0; i < 4; i++) a[i] = kb[(ty * 4 + i) * LD + d];
    float4 b4 = *(const float4*)&kcT[d * LD + tx * 4];
#pragma unroll
    for (int i = 0; i < 4; i++) {
      acc[i][0] += a[i] * b4.x; acc[i][1] += a[i] * b4.y;
      acc[i][2] += a[i] * b4.z; acc[i][3] += a[i] * b4.w;
    }
  }
#pragma unroll
  for (int i = 0; i < 4; i++)
#pragma unroll
    for (int j = 0; j < 4; j++) {
      int ii = ty * 4 + i, jj = tx * 4 + j;
      L[ii * LD + jj] = (ii > jj) ? acc[i][j] : 0.f;
    }
  __syncthreads();
  for (int i = 1; i < 64; i++) {
    if (tid < 128) {
      float s = 0.f;
      const float* Li = L + i * LD;
      for (int j = 0; j < i; j++) s += Li[j] * uw[j * 136 + tid];
      uw[i * 136 + tid] -= s;
    }
    __syncthreads();
  }
  float* dst = g_uw + (size_t)bx * 8192;
  for (int idx = tid; idx < 8192; idx += 256)
    dst[idx] = uw[(idx >> 7) * 136 + (idx & 127)];
}

// ---------------- state recurrence, e-split x4 (64 blocks) ----------------
__global__ __launch_bounds__(256) void recur_kernel() {
  __shared__ float S[64 * 17];
  __shared__ float up[64 * 17];
  __shared__ float w[64 * 68];
  __shared__ float kc[64 * 68];
  const int g = blockIdx.x >> 2, es = (blockIdx.x & 3) * 16;
  const int tid = threadIdx.x;
  const int col = tid & 15, rq = tid >> 4;
  for (int i = tid; i < 1024; i += 256) S[(i >> 4) * 17 + (i & 15)] = 0.f;
  __syncthreads();
  for (int ch = 0; ch < 16; ch++) {
    size_t bi = (size_t)(g * 16 + ch);
    const float* uwp = g_uw + bi * 8192;
    size_t kbase = ((size_t)g * 1024 + ch * 64) * 64;
    for (int idx = tid; idx < 4096; idx += 256) {
      int r = idx >> 6, c = idx & 63;
      w[r * 68 + c] = uwp[r * 128 + 64 + c];
      kc[r * 68 + c] = g_kl[kbase + idx];
    }
    for (int i = tid; i < 1024; i += 256) {
      int r = i >> 4, c = i & 15;
      g_Spre[bi * 4096 + r * 64 + es + c] = S[r * 17 + c];
    }
    __syncthreads();
    float a[4] = {};
#pragma unroll 8
    for (int d = 0; d < 64; d++) {
      float sv = S[d * 17 + col];
#pragma unroll
      for (int i = 0; i < 4; i++) a[i] += w[(rq * 4 + i) * 68 + d] * sv;
    }
    float upv[4];
#pragma unroll
    for (int i = 0; i < 4; i++) {
      upv[i] = uwp[(rq * 4 + i) * 128 + es + col] - a[i];
      up[(rq * 4 + i) * 17 + col] = upv[i];
      g_up[bi * 4096 + (rq * 4 + i) * 64 + es + col] = upv[i];
    }
    __syncthreads();
    float b4[4] = {};
#pragma unroll 8
    for (int c = 0; c < 64; c++) {
      float uv = up[c * 17 + col];
#pragma unroll
      for (int i = 0; i < 4; i++) b4[i] += kc[c * 68 + rq * 4 + i] * uv;
    }
#pragma unroll
    for (int i = 0; i < 4; i++) S[(rq * 4 + i) * 17 + col] += b4[i];
    __syncthreads();
  }
}

// ---------------- linear-branch output ----------------
__global__ __launch_bounds__(256) void olin_kernel() {
  extern __shared__ float sm_ol[];
  float* QT = sm_ol;
  float* KT = QT + 64 * LD;
  float* S = KT + 64 * LD;
  float* UP = S + 64 * LD;
  float* AT = UP + 64 * LD;
  const int bx = blockIdx.x;
  const int bh = bx >> 4, ch = bx & 15;
  const int b = bh >> 5, h = bh & 31;
  const int g = b * 8 + (h >> 2);
  const int tid = threadIdx.x, tx = tid & 15, ty = tid >> 4;
  size_t qbase = ((size_t)bh * 1024 + ch * 64) * 64;
  size_t kbase = ((size_t)g * 1024 + ch * 64) * 64;
  size_t sbase = (size_t)(g * 16 + ch) * 4096;
  for (int idx = tid; idx < 4096; idx += 256) {
    int r = idx >> 6, c = idx & 63;
    QT[c * LD + r] = g_ql[qbase + idx];
    KT[c * LD + r] = g_kl[kbase + idx];
    S[r * LD + c] = g_Spre[sbase + idx];
    UP[r * LD + c] = g_up[sbase + idx];
  }
  __syncthreads();
  float acc[4][4] = {};
#pragma unroll 8
  for (int d = 0; d < 64; d++) {
    float a[4];
#pragma unroll
    for (int i = 0; i < 4; i++) a[i] = QT[d * LD + ty * 4 + i];
    float4 b4 = *(const float4*)&KT[d * LD + tx * 4];
#pragma unroll
    for (int i = 0; i < 4; i++) {
      acc[i][0] += a[i] * b4.x; acc[i][1] += a[i] * b4.y;
      acc[i][2] += a[i] * b4.z; acc[i][3] += a[i] * b4.w;
    }
  }
#pragma unroll
  for (int i = 0; i < 4; i++)
#pragma unroll
    for (int j = 0; j < 4; j++) {
      int ii = ty * 4 + i, jj = tx * 4 + j;
      AT[ii * LD + jj] = (jj <= ii) ? acc[i][j] : 0.f;
    }
  __syncthreads();
  float o[4][4] = {};
#pragma unroll 8
  for (int d = 0; d < 64; d++) {
    float a[4];
#pragma unroll
    for (int i = 0; i < 4; i++) a[i] = QT[d * LD + ty * 4 + i];
    float4 b4 = *(const float4*)&S[d * LD + tx * 4];
#pragma unroll
    for (int i = 0; i < 4; i++) {
      o[i][0] += a[i] * b4.x; o[i][1] += a[i] * b4.y;
      o[i][2] += a[i] * b4.z; o[i][3] += a[i] * b4.w;
    }
  }
#pragma unroll 8
  for (int j0 = 0; j0 < 64; j0++) {
    float a[4];
#pragma unroll
    for (int i = 0; i < 4; i++) a[i] = AT[(ty * 4 + i) * LD + j0];
    float4 b4 = *(const float4*)&UP[j0 * LD + tx * 4];
#pragma unroll
    for (int i = 0; i < 4; i++) {
      o[i][0] += a[i] * b4.x; o[i][1] += a[i] * b4.y;
      o[i][2] += a[i] * b4.z; o[i][3] += a[i] * b4.w;
    }
  }
#pragma unroll
  for (int i = 0; i < 4; i++) {
    size_t ob = ((size_t)(b * 1024 + ch * 64 + ty * 4 + i)) * 2048 + h * 64 + tx * 4;
    *(float4*)&g_olin[ob] = make_float4(o[i][0], o[i][1], o[i][2], o[i][3]);
  }
}

// ---------------- one-pass HMMA attention (no max subtraction; deferred norm) ----------------
__global__ __launch_bounds__(256) void attn_hmma(float* __restrict__ attn_out,
                                                 int write_attn) {
  extern __shared__ __align__(128) char sm[];
  const uint32_t sb = smem_u32(sm);
  const int qt = blockIdx.x, h = blockIdx.y, b = blockIdx.z;
  const int hk = h >> 2;
  const int tid = threadIdx.x, wid = tid >> 5, lane = tid & 31;
  const int wy = wid & 3, wx = wid >> 2;
  const uint32_t QH = 0, QL = 9216;
  const uint32_t ST0 = 18432, ST1 = 55296;  // each: KH +0, KL +9216, VH +18432, VL +27648
  const uint32_t PH = 92160, PL = 101376, RED = 110592, REDT = 111104;
  float* REDp = (float*)(sm + RED);
  float* REDt = (float*)(sm + REDT);
  const size_t qbase = ((size_t)((b * 32 + h) * 1024) + (size_t)qt * 64) * 64;
  const size_t kvb = ((size_t)((b * 8 + hk) * 1024)) * 64;

  // Q + stage0 (kt=0), single commit group
  {
#pragma unroll
    for (int i = 0; i < 4; i++) {
      int idx = i * 256 + tid;
      int mat = idx >> 9;
      int ri = idx & 511;
      int row = ri >> 3, seg = ri & 7;
      const char* g =
          (const char*)((mat ? g_qsl : g_qsh) + qbase + (size_t)row * 64 + seg * 8);
      CPA16(sb + (mat ? QL : QH) + row * 144 + seg * 16, g);
    }
#pragma unroll
    for (int i = 0; i < 8; i++) {
      int idx = i * 256 + tid;
      int mat = idx >> 9;
      int ri = idx & 511;
      int row = ri >> 3, seg = ri & 7;
      const __nv_bfloat16* sp = (mat == 0)   ? g_ksh
                                : (mat == 1) ? g_ksl
                                : (mat == 2) ? g_vsh
                                             : g_vsl;
      const char* g = (const char*)(sp + kvb + (size_t)row * 64 + seg * 8);
      CPA16(sb + ST0 + mat * 9216 + row * 144 + seg * 16, g);
    }
    CPCOMMIT();
  }

  const int r0i = wy * 16 + (lane >> 2);
  float l0 = 0.f, l1 = 0.f;
  float o[4][4] = {};
  const size_t arow0 = (size_t)(b * 32 + h) * 1024 + (size_t)qt * 64;

  for (int kt = 0; kt <= qt; kt++) {
    __syncthreads();  // all warps done with both stages' prior reads
    if (kt < qt) {
      uint32_t nst = ((kt + 1) & 1) ? ST1 : ST0;
#pragma unroll
      for (int i = 0; i < 8; i++) {
        int idx = i * 256 + tid;
        int mat = idx >> 9;
        int ri = idx & 511;
        int row = ri >> 3, seg = ri & 7;
        const __nv_bfloat16* sp = (mat == 0)   ? g_ksh
                                  : (mat == 1) ? g_ksl
                                  : (mat == 2) ? g_vsh
                                               : g_vsl;
        const char* g =
            (const char*)(sp + kvb + (size_t)((kt + 1) * 64 + row) * 64 + seg * 8);
        CPA16(sb + nst + mat * 9216 + row * 144 + seg * 16, g);
      }
      CPCOMMIT();
      asm volatile("cp.async.wait_group 1;");
    } else {
      asm volatile("cp.async.wait_group 0;");
    }
    __syncthreads();
    const uint32_t cst = (kt & 1) ? ST1 : ST0;
    float s[4][4] = {};
#pragma unroll
    for (int ks = 0; ks < 4; ks++) {
      uint32_t qhf[4], qlf[4], kf[4][2], klf[4][2];
      uint32_t qoff = (wy * 16 + (lane & 15)) * 144 + ks * 32 + (lane >> 4) * 16;
      LDSM4(qhf, sb + QH + qoff);
      LDSM4(qlf, sb + QL + qoff);
#pragma unroll
      for (int np = 0; np < 2; np++) {
        int j = lane >> 3;
        uint32_t off =
            (wx * 32 + np * 16 + (j >> 1) * 8 + (lane & 7)) * 144 + ks * 32 + (j & 1) * 16;
        LDSM4(kf[2 * np], sb + cst + off);
        LDSM4(klf[2 * np], sb + cst + 9216 + off);
      }
#pragma unroll
      for (int sub = 0; sub < 4; sub++) {
        MMA16816(s[sub], qhf, kf[sub]);
        MMA16816(s[sub], qhf, klf[sub]);
        MMA16816(s[sub], qlf, kf[sub]);
      }
    }
    if (kt == qt) {
      int gr = qt * 64 + r0i;
#pragma unroll
      for (int sub = 0; sub < 4; sub++) {
        int gc = kt * 64 + wx * 32 + sub * 8 + (lane & 3) * 2;
        if (gc > gr) s[sub][0] = -1e30f;
        if (gc + 1 > gr) s[sub][1] = -1e30f;
        if (gc > gr + 8) s[sub][2] = -1e30f;
        if (gc + 1 > gr + 8) s[sub][3] = -1e30f;
      }
    }
#pragma unroll
    for (int sub = 0; sub < 4; sub++) {
      float p0 = __expf(s[sub][0]);
      float p1 = __expf(s[sub][1]);
      float p2 = __expf(s[sub][2]);
      float p3 = __expf(s[sub][3]);
      l0 += p0 + p1;
      l1 += p2 + p3;
      int cl = wx * 32 + sub * 8 + (lane & 3) * 2;
      if (write_attn) {
        int col = kt * 64 + cl;
        *(float2*)&attn_out[(arow0 + r0i) * 1024 + col] = make_float2(p0, p1);
        *(float2*)&attn_out[(arow0 + r0i + 8) * 1024 + col] = make_float2(p2, p3);
      }
      __nv_bfloat16 h0 = __float2bfloat16(p0), h1 = __float2bfloat16(p1);
      __nv_bfloat16 h2 = __float2bfloat16(p2), h3 = __float2bfloat16(p3);
      *(__nv_bfloat162*)(sm + PH + r0i * 144 + cl * 2) = __halves2bfloat162(h0, h1);
      *(__nv_bfloat162*)(sm + PH + (r0i + 8) * 144 + cl * 2) = __halves2bfloat162(h2, h3);
      *(__nv_bfloat162*)(sm + PL + r0i * 144 + cl * 2) = __halves2bfloat162(
          __float2bfloat16(p0 - __bfloat162float(h0)),
          __float2bfloat16(p1 - __bfloat162float(h1)));
      *(__nv_bfloat162*)(sm + PL + (r0i + 8) * 144 + cl * 2) = __halves2bfloat162(
          __float2bfloat16(p2 - __bfloat162float(h2)),
          __float2bfloat16(p3 - __bfloat162float(h3)));
    }
    __syncthreads();
#pragma unroll
    for (int ks = 0; ks < 4; ks++) {
      uint32_t pf[4], plf[4], vf[4][2], vlf[4][2];
      uint32_t poff = (wy * 16 + (lane & 15)) * 144 + ks * 32 + (lane >> 4) * 16;
      LDSM4(pf, sb + PH + poff);
      LDSM4(plf, sb + PL + poff);
#pragma unroll
      for (int np = 0; np < 2; np++) {
        int g2 = lane >> 3;
        uint32_t off = (ks * 16 + (g2 & 1) * 8 + (lane & 7)) * 144 +
                       (wx * 32 + np * 16) * 2 + (g2 >> 1) * 16;
        LDSM4T(vf[2 * np], sb + cst + 18432 + off);
        LDSM4T(vlf[2 * np], sb + cst + 27648 + off);
      }
#pragma unroll
      for (int sub = 0; sub < 4; sub++) {
        MMA16816(o[sub], pf, vf[sub]);
        MMA16816(o[sub], plf, vf[sub]);
        MMA16816(o[sub], pf, vlf[sub]);
      }
    }
  }

  // final l reduction (once)
  l0 += __shfl_xor_sync(0xffffffffu, l0, 1);
  l0 += __shfl_xor_sync(0xffffffffu, l0, 2);
  l1 += __shfl_xor_sync(0xffffffffu, l1, 1);
  l1 += __shfl_xor_sync(0xffffffffu, l1, 2);
  if ((lane & 3) == 0) {
    REDp[r0i * 2 + wx] = l0;
    REDp[(r0i + 8) * 2 + wx] = l1;
  }
  __syncthreads();
  if (tid < 64) {
    float lt = REDp[tid * 2] + REDp[tid * 2 + 1];
    REDt[tid] = lt;
    g_lsum[(size_t)(b * 32 + h) * 1024 + qt * 64 + tid] = lt;
  }
  __syncthreads();
  float invl0 = 1.f / REDt[r0i];
  float invl1 = 1.f / REDt[r0i + 8];

  // zero upper-triangle tiles
  if (write_attn) {
    for (int kt = qt + 1; kt < 16; kt++) {
#pragma unroll
      for (int i = 0; i < 4; i++) {
        int idx = i * 256 + tid;
        int row = idx >> 4, c4 = (idx & 15) * 4;
        *(float4*)&attn_out[(arow0 + row) * 1024 + kt * 64 + c4] =
            make_float4(0.f, 0.f, 0.f, 0.f);
      }
    }
  }

  // epilogue: omix = 0.5*(olin + o/l); write bf16 hi/lo directly for final GEMM
#pragma unroll
  for (int sub = 0; sub < 4; sub++) {
    int gr = qt * 64 + r0i;
    int col = wx * 32 + sub * 8 + (lane & 3) * 2;
    size_t ob = ((size_t)(b * 1024 + gr)) * 2048 + h * 64 + col;
    float2 ol = *(const float2*)&g_olin[ob];
    float m0 = 0.5f * (ol.x + o[sub][0] * invl0);
    float m1 = 0.5f * (ol.y + o[sub][1] * invl0);
    __nv_bfloat16 h0 = __float2bfloat16(m0), h1 = __float2bfloat16(m1);
    *(__nv_bfloat162*)&g_Ah[ob] = __halves2bfloat162(h0, h1);
    *(__nv_bfloat162*)&g_Al[ob] =
        __halves2bfloat162(__float2bfloat16(m0 - __bfloat162float(h0)),
                           __float2bfloat16(m1 - __bfloat162float(h1)));
    size_t ob2 = ((size_t)(b * 1024 + gr + 8)) * 2048 + h * 64 + col;
    float2 ol2 = *(const float2*)&g_olin[ob2];
    float m2 = 0.5f * (ol2.x + o[sub][2] * invl1);
    float m3 = 0.5f * (ol2.y + o[sub][3] * invl1);
    __nv_bfloat16 h2 = __float2bfloat16(m2), h3 = __float2bfloat16(m3);
    *(__nv_bfloat162*)&g_Ah[ob2] = __halves2bfloat162(h2, h3);
    *(__nv_bfloat162*)&g_Al[ob2] =
        __halves2bfloat162(__float2bfloat16(m2 - __bfloat162float(h2)),
                           __float2bfloat16(m3 - __bfloat162float(h3)));
  }
}

// ---------------- normalize attn_weights lower triangle ----------------
__global__ __launch_bounds__(256) void rescale_kernel(float* __restrict__ attn) {
  const int qt = blockIdx.x, bh = blockIdx.y;
  __shared__ float inv[64];
  if (threadIdx.x < 64)
    inv[threadIdx.x] = 1.f / g_lsum[(size_t)bh * 1024 + qt * 64 + threadIdx.x];
  __syncthreads();
  const int ncol4 = (qt + 1) * 16;
  for (int r = 0; r < 64; r++) {
    float iv = inv[r];
    float4* rowp = (float4*)(attn + ((size_t)bh * 1024 + qt * 64 + r) * 1024);
    for (int c = threadIdx.x; c < ncol4; c += 256) {
      float4 v = rowp[c];
      v.x *= iv; v.y *= iv; v.z *= iv; v.w *= iv;
      rowp[c] = v;
    }
  }
}

extern "C" void kernel_launch(void* const* d_in, const int* in_sizes, int n_in,
                              void* d_out, int out_size) {
  const float* hidden = (const float*)d_in[0];
  const float* Wq = (const float*)d_in[1];
  const float* Wk = (const float*)d_in[2];
  const float* Wv = (const float*)d_in[3];
  const float* Wo = (const float*)d_in[4];
  float* out = (float*)d_out;
  float* attn_out = out + 4194304;
  int write_attn = (out_size >= 71303168) ? 1 : 0;

  float* gq;  cudaGetSymbolAddress((void**)&gq, g_q);
  float* gk;  cudaGetSymbolAddress((void**)&gk, g_k);
  float* gv;  cudaGetSymbolAddress((void**)&gv, g_v);
  __nv_bfloat16 *gAh, *gAl, *gWqh, *gWql, *gWkh, *gWkl, *gWvh, *gWvl, *gWoh, *gWol;
  cudaGetSymbolAddress((void**)&gAh, g_Ah);
  cudaGetSymbolAddress((void**)&gAl, g_Al);
  cudaGetSymbolAddress((void**)&gWqh, g_Wqh);
  cudaGetSymbolAddress((void**)&gWql, g_Wql);
  cudaGetSymbolAddress((void**)&gWkh, g_Wkh);
  cudaGetSymbolAddress((void**)&gWkl, g_Wkl);
  cudaGetSymbolAddress((void**)&gWvh, g_Wvh);
  cudaGetSymbolAddress((void**)&gWvl, g_Wvl);
  cudaGetSymbolAddress((void**)&gWoh, g_Woh);
  cudaGetSymbolAddress((void**)&gWol, g_Wol);

  static const int smem_uw = (3 * 64 * LD + 64 * 136) * 4;
  static const int smem_ol = 5 * 64 * LD * 4;
  static const int smem_g = 2 * 40960;
  static const int smem_at = 111616;
  cudaFuncSetAttribute(uw_kernel, cudaFuncAttributeMaxDynamicSharedMemorySize, smem_uw);
  cudaFuncSetAttribute(olin_kernel, cudaFuncAttributeMaxDynamicSharedMemorySize, smem_ol);
  cudaFuncSetAttribute(hmma_gemm, cudaFuncAttributeMaxDynamicSharedMemorySize, smem_g);
  cudaFuncSetAttribute(attn_hmma, cudaFuncAttributeMaxDynamicSharedMemorySize, smem_at);

  split_kernel<<<4096, 256>>>(hidden, gAh, gAl, 1048576);
  splitT_kernel<<<dim3(64, 64), 256>>>(Wq, gWqh, gWql, 2048, 2048);
  splitT_kernel<<<dim3(16, 64), 256>>>(Wk, gWkh, gWkl, 2048, 512);
  splitT_kernel<<<dim3(16, 64), 256>>>(Wv, gWvh, gWvl, 2048, 512);
  splitT_kernel<<<dim3(64, 64), 256>>>(Wo, gWoh, gWol, 2048, 2048);

  hmma_gemm<<<dim3(16, 16), 256, smem_g>>>(gAh, gAl, gWqh, gWql, gq, 2048, 2048);
  hmma_gemm<<<dim3(4, 16), 256, smem_g>>>(gAh, gAl, gWkh, gWkl, gk, 512, 2048);
  hmma_gemm<<<dim3(4, 16), 256, smem_g>>>(gAh, gAl, gWvh, gWvl, gv, 512, 2048);

  prep_kernel<<<10240, 256>>>();
  uw_kernel<<<256, 256, smem_uw>>>();
  recur_kernel<<<64, 256>>>();
  olin_kernel<<<1024, 256, smem_ol>>>();
  attn_hmma<<<dim3(16, 32, 2), 256, smem_at>>>(attn_out, write_attn);
  if (write_attn) rescale_kernel<<<dim3(16, 64), 256>>>(attn_out);

  hmma_gemm<<<dim3(16, 16), 256, smem_g>>>(gAh, gAl, gWoh, gWol, out, 2048, 2048);
}

// round 12
// speedup vs baseline: 1.0687x; 1.0687x over previous
#include <cuda_runtime.h>
#include <cuda_bf16.h>
#include <cstdint>
#include <math.h>

#define LD 68

// ---------------- scratch ----------------
__device__ float g_q[2048 * 2048];
__device__ float g_k[2048 * 512];
__device__ float g_v[2048 * 512];
__device__ float g_ql[2 * 32 * 1024 * 64];
__device__ float g_kl[2 * 8 * 1024 * 64];
__device__ float g_gl[2 * 8 * 1024 * 64];
__device__ float g_vh[2 * 8 * 1024 * 64];
__device__ float g_uw[2 * 8 * 16 * 64 * 128];
__device__ float g_up[2 * 8 * 16 * 64 * 64];
__device__ float g_Spre[2 * 8 * 16 * 64 * 64];
__device__ float g_olin[2048 * 2048];

__device__ __nv_bfloat16 g_Ah[2048 * 2048];
__device__ __nv_bfloat16 g_Al[2048 * 2048];
__device__ __nv_bfloat16 g_Wqh[2048 * 2048];
__device__ __nv_bfloat16 g_Wql[2048 * 2048];
__device__ __nv_bfloat16 g_Wkh[512 * 2048];
__device__ __nv_bfloat16 g_Wkl[512 * 2048];
__device__ __nv_bfloat16 g_Wvh[512 * 2048];
__device__ __nv_bfloat16 g_Wvl[512 * 2048];
__device__ __nv_bfloat16 g_Woh[2048 * 2048];
__device__ __nv_bfloat16 g_Wol[2048 * 2048];

// bf16 split q/k/v for HMMA attention (head-major)
__device__ __nv_bfloat16 g_qsh[2 * 32 * 1024 * 64];
__device__ __nv_bfloat16 g_qsl[2 * 32 * 1024 * 64];
__device__ __nv_bfloat16 g_ksh[2 * 8 * 1024 * 64];
__device__ __nv_bfloat16 g_ksl[2 * 8 * 1024 * 64];
__device__ __nv_bfloat16 g_vsh[2 * 8 * 1024 * 64];
__device__ __nv_bfloat16 g_vsl[2 * 8 * 1024 * 64];

__device__ __forceinline__ uint32_t smem_u32(const void* p) {
  uint32_t a;
  asm("{ .reg .u64 t; cvta.to.shared.u64 t, %1; cvt.u32.u64 %0, t; }" : "=r"(a) : "l"(p));
  return a;
}

#define LDSM4(r, addr)                                                        \
  asm volatile("ldmatrix.sync.aligned.m8n8.x4.shared.b16 {%0,%1,%2,%3}, [%4];"\
               : "=r"((r)[0]), "=r"((r)[1]), "=r"((r)[2]), "=r"((r)[3])       \
               : "r"(addr))

#define LDSM4T(r, addr)                                                       \
  asm volatile(                                                               \
      "ldmatrix.sync.aligned.m8n8.x4.trans.shared.b16 {%0,%1,%2,%3}, [%4];"   \
      : "=r"((r)[0]), "=r"((r)[1]), "=r"((r)[2]), "=r"((r)[3])                \
      : "r"(addr))

#define MMA16816(c, a, b)                                                     \
  asm volatile(                                                               \
      "mma.sync.aligned.m16n8k16.row.col.f32.bf16.bf16.f32 "                  \
      "{%0,%1,%2,%3},{%4,%5,%6,%7},{%8,%9},{%0,%1,%2,%3};"                    \
      : "+f"((c)[0]), "+f"((c)[1]), "+f"((c)[2]), "+f"((c)[3])                \
      : "r"((a)[0]), "r"((a)[1]), "r"((a)[2]), "r"((a)[3]),                   \
        "r"((b)[0]), "r"((b)[1]))

#define CPA16(dst, src)                                                       \
  asm volatile("cp.async.cg.shared.global [%0], [%1], 16;" :: "r"(dst), "l"(src))
#define CPCOMMIT() asm volatile("cp.async.commit_group;")

// ---------------- split kernels ----------------
__global__ __launch_bounds__(256) void split_kernel(
    const float* __restrict__ x, __nv_bfloat16* __restrict__ hi,
    __nv_bfloat16* __restrict__ lo, int n4) {
  int i = blockIdx.x * 256 + threadIdx.x;
  if (i >= n4) return;
  float4 v = ((const float4*)x)[i];
  __nv_bfloat16 h0 = __float2bfloat16(v.x), h1 = __float2bfloat16(v.y);
  __nv_bfloat16 h2 = __float2bfloat16(v.z), h3 = __float2bfloat16(v.w);
  __nv_bfloat16 l0 = __float2bfloat16(v.x - __bfloat162float(h0));
  __nv_bfloat16 l1 = __float2bfloat16(v.y - __bfloat162float(h1));
  __nv_bfloat16 l2 = __float2bfloat16(v.z - __bfloat162float(h2));
  __nv_bfloat16 l3 = __float2bfloat16(v.w - __bfloat162float(h3));
  __nv_bfloat162* H = (__nv_bfloat162*)hi;
  __nv_bfloat162* L = (__nv_bfloat162*)lo;
  H[2 * i] = __halves2bfloat162(h0, h1);
  H[2 * i + 1] = __halves2bfloat162(h2, h3);
  L[2 * i] = __halves2bfloat162(l0, l1);
  L[2 * i + 1] = __halves2bfloat162(l2, l3);
}

__global__ __launch_bounds__(256) void splitT_kernel(
    const float* __restrict__ W, __nv_bfloat16* __restrict__ hiT,
    __nv_bfloat16* __restrict__ loT, int K, int N) {
  __shared__ float t[32][33];
  int nx = blockIdx.x * 32, ky = blockIdx.y * 32;
  int tx = threadIdx.x & 31, ty = threadIdx.x >> 5;
  for (int j = ty; j < 32; j += 8)
    t[j][tx] = W[(size_t)(ky + j) * N + nx + tx];
  __syncthreads();
  for (int j = ty; j < 32; j += 8) {
    float v = t[tx][j];
    __nv_bfloat16 h = __float2bfloat16(v);
    __nv_bfloat16 l = __float2bfloat16(v - __bfloat162float(h));
    size_t o = (size_t)(nx + j) * K + ky + tx;
    hiT[o] = h;
    loT[o] = l;
  }
}

// ---------------- HMMA bf16 split GEMM body ----------------
__device__ __forceinline__ void gemm_body(
    const __nv_bfloat16* __restrict__ Ah, const __nv_bfloat16* __restrict__ Al,
    const __nv_bfloat16* __restrict__ Bh, const __nv_bfloat16* __restrict__ Bl,
    float* __restrict__ C, int N, int K, int m0, int n0, uint32_t sb) {
  const int tid = threadIdx.x, wid = tid >> 5, lane = tid & 31;
  const int wy = wid & 3, wx = wid >> 2;
  const int nchunks = K >> 5;
  const __nv_bfloat16* srcs[4] = {Ah, Al, Bh, Bl};

  float acc[2][8][4];
#pragma unroll
  for (int mt = 0; mt < 2; mt++)
#pragma unroll
    for (int nt = 0; nt < 8; nt++)
#pragma unroll
      for (int e = 0; e < 4; e++) acc[mt][nt][e] = 0.f;

#pragma unroll
  for (int pc = 0; pc < 2; pc++) {
    uint32_t base = sb + pc * 40960;
#pragma unroll
    for (int it = 0; it < 8; it++) {
      int idx = it * 256 + tid;
      int mat = idx >> 9;
      int r = (idx >> 2) & 127;
      int seg = idx & 3;
      int grow = (mat < 2 ? m0 : n0) + r;
      const char* g = (const char*)(srcs[mat] + (size_t)grow * K + pc * 32) + seg * 16;
      CPA16(base + mat * 10240 + r * 80 + seg * 16, g);
    }
    CPCOMMIT();
  }

  for (int kc = 0; kc < nchunks; kc++) {
    if (kc == nchunks - 1)
      asm volatile("cp.async.wait_group 0;");
    else
      asm volatile("cp.async.wait_group 1;");
    __syncthreads();
    const uint32_t base = sb + (kc & 1) * 40960;
#pragma unroll
    for (int ks = 0; ks < 2; ks++) {
      uint32_t ah[2][4], al[2][4], bh[8][2], bl[8][2];
#pragma unroll
      for (int mt = 0; mt < 2; mt++) {
        int row = wy * 32 + mt * 16 + (lane & 15);
        uint32_t off = row * 80 + (ks * 16 + (lane >> 4) * 8) * 2;
        LDSM4(ah[mt], base + off);
        LDSM4(al[mt], base + 10240 + off);
      }
#pragma unroll
      for (int np = 0; np < 4; np++) {
        int j = lane >> 3;
        int row = wx * 64 + np * 16 + (j >> 1) * 8 + (lane & 7);
        uint32_t off = row * 80 + (ks * 16 + (j & 1) * 8) * 2;
        LDSM4(bh[2 * np], base + 20480 + off);
        LDSM4(bl[2 * np], base + 30720 + off);
      }
#pragma unroll
      for (int mt = 0; mt < 2; mt++)
#pragma unroll
        for (int nt = 0; nt < 8; nt++) {
          MMA16816(acc[mt][nt], ah[mt], bh[nt]);
          MMA16816(acc[mt][nt], ah[mt], bl[nt]);
          MMA16816(acc[mt][nt], al[mt], bh[nt]);
        }
    }
    __syncthreads();
    if (kc + 2 < nchunks) {
      uint32_t lbase = sb + (kc & 1) * 40960;
#pragma unroll
      for (int it = 0; it < 8; it++) {
        int idx = it * 256 + tid;
        int mat = idx >> 9;
        int r = (idx >> 2) & 127;
        int seg = idx & 3;
        int grow = (mat < 2 ? m0 : n0) + r;
        const char* g =
            (const char*)(srcs[mat] + (size_t)grow * K + (kc + 2) * 32) + seg * 16;
        CPA16(lbase + mat * 10240 + r * 80 + seg * 16, g);
      }
      CPCOMMIT();
    }
  }

#pragma unroll
  for (int mt = 0; mt < 2; mt++)
#pragma unroll
    for (int nt = 0; nt < 8; nt++) {
      int row = m0 + wy * 32 + mt * 16 + (lane >> 2);
      int col = n0 + wx * 64 + nt * 8 + (lane & 3) * 2;
      *(float2*)&C[(size_t)row * N + col] =
          make_float2(acc[mt][nt][0], acc[mt][nt][1]);
      *(float2*)&C[(size_t)(row + 8) * N + col] =
          make_float2(acc[mt][nt][2], acc[mt][nt][3]);
    }
}

__global__ __launch_bounds__(256) void hmma_gemm(
    const __nv_bfloat16* __restrict__ Ah, const __nv_bfloat16* __restrict__ Al,
    const __nv_bfloat16* __restrict__ Bh, const __nv_bfloat16* __restrict__ Bl,
    float* __restrict__ C, int N, int K) {
  extern __shared__ __align__(128) char smem[];
  gemm_body(Ah, Al, Bh, Bl, C, N, K, blockIdx.y * 128, blockIdx.x * 128,
            smem_u32(smem));
}

// fused Q/K/V projection: grid.x = 16(Q) + 4(K) + 4(V) = 24
__global__ __launch_bounds__(256) void hmma_gemm_qkv() {
  extern __shared__ __align__(128) char smem[];
  const int bx = blockIdx.x;
  const __nv_bfloat16 *Bh, *Bl;
  float* C;
  int N, n0;
  if (bx < 16) {
    Bh = g_Wqh; Bl = g_Wql; C = g_q; N = 2048; n0 = bx * 128;
  } else if (bx < 20) {
    Bh = g_Wkh; Bl = g_Wkl; C = g_k; N = 512; n0 = (bx - 16) * 128;
  } else {
    Bh = g_Wvh; Bl = g_Wvl; C = g_v; N = 512; n0 = (bx - 20) * 128;
  }
  gemm_body(g_Ah, g_Al, Bh, Bl, C, N, 2048, blockIdx.y * 128, n0,
            smem_u32(smem));
}

// ---------------- feature maps + bf16 splits ----------------
__global__ __launch_bounds__(256) void prep_kernel() {
  int gw = (blockIdx.x * 256 + threadIdx.x) >> 5;
  int lane = threadIdx.x & 31;
  if (gw < 65536) {
    int token = gw >> 5, h = gw & 31;
    const float* src = g_q + (size_t)token * 2048 + h * 64;
    float x0 = src[lane], x1 = src[lane + 32];
    float mx = fmaxf(x0, x1);
#pragma unroll
    for (int o = 16; o > 0; o >>= 1) mx = fmaxf(mx, __shfl_xor_sync(0xffffffffu, mx, o));
    float e0 = __expf(x0 - mx), e1 = __expf(x1 - mx);
    float s = e0 + e1;
#pragma unroll
    for (int o = 16; o > 0; o >>= 1) s += __shfl_xor_sync(0xffffffffu, s, o);
    float inv = 1.f / s;
    int b = token >> 10, n = token & 1023;
    size_t hb = ((size_t)((b * 32 + h) * 1024 + n)) * 64;
    g_ql[hb + lane] = e0 * inv;
    g_ql[hb + lane + 32] = e1 * inv;
    float s0 = x0 * 0.125f, s1 = x1 * 0.125f;
    __nv_bfloat16 h0 = __float2bfloat16(s0), h1 = __float2bfloat16(s1);
    g_qsh[hb + lane] = h0;
    g_qsh[hb + lane + 32] = h1;
    g_qsl[hb + lane] = __float2bfloat16(s0 - __bfloat162float(h0));
    g_qsl[hb + lane + 32] = __float2bfloat16(s1 - __bfloat162float(h1));
  } else {
    int j = gw - 65536;
    int token = j >> 3, hk = j & 7;
    const float* ks = g_k + (size_t)token * 512 + hk * 64;
    const float* vs = g_v + (size_t)token * 512 + hk * 64;
    float x0 = ks[lane], x1 = ks[lane + 32];
    float v0 = vs[lane], v1 = vs[lane + 32];
    float mx = fmaxf(x0, x1);
#pragma unroll
    for (int o = 16; o > 0; o >>= 1) mx = fmaxf(mx, __shfl_xor_sync(0xffffffffu, mx, o));
    float e0 = __expf(x0 - mx), e1 = __expf(x1 - mx);
    float s = e0 + e1;
#pragma unroll
    for (int o = 16; o > 0; o >>= 1) s += __shfl_xor_sync(0xffffffffu, s, o);
    float inv = 1.f / s;
    int b = token >> 10, n = token & 1023;
    size_t base = ((size_t)((b * 8 + hk) * 1024 + n)) * 64;
    g_kl[base + lane] = e0 * inv;
    g_kl[base + lane + 32] = e1 * inv;
    g_gl[base + lane] = (fminf(x0, 0.f) - log1pf(__expf(-fabsf(x0)))) * 0.0625f;
    g_gl[base + lane + 32] = (fminf(x1, 0.f) - log1pf(__expf(-fabsf(x1)))) * 0.0625f;
    g_vh[base + lane] = v0;
    g_vh[base + lane + 32] = v1;
    __nv_bfloat16 kh0 = __float2bfloat16(x0), kh1 = __float2bfloat16(x1);
    g_ksh[base + lane] = kh0;
    g_ksh[base + lane + 32] = kh1;
    g_ksl[base + lane] = __float2bfloat16(x0 - __bfloat162float(kh0));
    g_ksl[base + lane + 32] = __float2bfloat16(x1 - __bfloat162float(kh1));
    __nv_bfloat16 vh0 = __float2bfloat16(v0), vh1 = __float2bfloat16(v1);
    g_vsh[base + lane] = vh0;
    g_vsh[base + lane + 32] = vh1;
    g_vsl[base + lane] = __float2bfloat16(v0 - __bfloat162float(vh0));
    g_vsl[base + lane + 32] = __float2bfloat16(v1 - __bfloat162float(vh1));
  }
}

// ---------------- per-chunk u,w ----------------
__global__ __launch_bounds__(256) void uw_kernel() {
  extern __shared__ float sm_uw[];
  float* kcT = sm_uw;
  float* kb = kcT + 64 * LD;
  float* L = kb + 64 * LD;
  float* uw = L + 64 * LD;
  const int bx = blockIdx.x;
  const int g = bx >> 4, ch = bx & 15;
  const int tid = threadIdx.x, tx = tid & 15, ty = tid >> 4;
  size_t base = ((size_t)g * 1024 + ch * 64) * 64;
  for (int idx = tid; idx < 4096; idx += 256) {
    int r = idx >> 6, c = idx & 63;
    float kv = g_kl[base + idx];
    float gv = g_gl[base + idx];
    float vv = g_vh[base + idx];
    kcT[c * LD + r] = kv;
    float kbv = kv * gv;
    kb[r * LD + c] = kbv;
    uw[r * 136 + c] = vv * gv;
    uw[r * 136 + 64 + c] = kbv;
  }
  __syncthreads();
  float acc[4][4] = {};
#pragma unroll 8
  for (int d = 0; d < 64; d++) {
    float a[4];
#pragma unroll
    for (int i = 0; i < 4; i++) a[i] = kb[(ty * 4 + i) * LD + d];
    float4 b4 = *(const float4*)&kcT[d * LD + tx * 4];
#pragma unroll
    for (int i = 0; i < 4; i++) {
      acc[i][0] += a[i] * b4.x; acc[i][1] += a[i] * b4.y;
      acc[i][2] += a[i] * b4.z; acc[i][3] += a[i] * b4.w;
    }
  }
#pragma unroll
  for (int i = 0; i < 4; i++)
#pragma unroll
    for (int j = 0; j < 4; j++) {
      int ii = ty * 4 + i, jj = tx * 4 + j;
      L[ii * LD + jj] = (ii > jj) ? acc[i][j] : 0.f;
    }
  __syncthreads();
  for (int i = 1; i < 64; i++) {
    if (tid < 128) {
      float s = 0.f;
      const float* Li = L + i * LD;
      for (int j = 0; j < i; j++) s += Li[j] * uw[j * 136 + tid];
      uw[i * 136 + tid] -= s;
    }
    __syncthreads();
  }
  float* dst = g_uw + (size_t)bx * 8192;
  for (int idx = tid; idx < 8192; idx += 256)
    dst[idx] = uw[(idx >> 7) * 136 + (idx & 127)];
}

// ---------------- state recurrence, e-split x4 (64 blocks) ----------------
__global__ __launch_bounds__(256) void recur_kernel() {
  __shared__ float S[64 * 17];
  __shared__ float up[64 * 17];
  __shared__ float w[64 * 68];
  __shared__ float kc[64 * 68];
  const int g = blockIdx.x >> 2, es = (blockIdx.x & 3) * 16;
  const int tid = threadIdx.x;
  const int col = tid & 15, rq = tid >> 4;
  for (int i = tid; i < 1024; i += 256) S[(i >> 4) * 17 + (i & 15)] = 0.f;
  __syncthreads();
  for (int ch = 0; ch < 16; ch++) {
    size_t bi = (size_t)(g * 16 + ch);
    const float* uwp = g_uw + bi * 8192;
    size_t kbase = ((size_t)g * 1024 + ch * 64) * 64;
    for (int idx = tid; idx < 4096; idx += 256) {
      int r = idx >> 6, c = idx & 63;
      w[r * 68 + c] = uwp[r * 128 + 64 + c];
      kc[r * 68 + c] = g_kl[kbase + idx];
    }
    for (int i = tid; i < 1024; i += 256) {
      int r = i >> 4, c = i & 15;
      g_Spre[bi * 4096 + r * 64 + es + c] = S[r * 17 + c];
    }
    __syncthreads();
    float a[4] = {};
#pragma unroll 8
    for (int d = 0; d < 64; d++) {
      float sv = S[d * 17 + col];
#pragma unroll
      for (int i = 0; i < 4; i++) a[i] += w[(rq * 4 + i) * 68 + d] * sv;
    }
    float upv[4];
#pragma unroll
    for (int i = 0; i < 4; i++) {
      upv[i] = uwp[(rq * 4 + i) * 128 + es + col] - a[i];
      up[(rq * 4 + i) * 17 + col] = upv[i];
      g_up[bi * 4096 + (rq * 4 + i) * 64 + es + col] = upv[i];
    }
    __syncthreads();
    float b4[4] = {};
#pragma unroll 8
    for (int c = 0; c < 64; c++) {
      float uv = up[c * 17 + col];
#pragma unroll
      for (int i = 0; i < 4; i++) b4[i] += kc[c * 68 + rq * 4 + i] * uv;
    }
#pragma unroll
    for (int i = 0; i < 4; i++) S[(rq * 4 + i) * 17 + col] += b4[i];
    __syncthreads();
  }
}

// ---------------- linear-branch output ----------------
__global__ __launch_bounds__(256) void olin_kernel() {
  extern __shared__ float sm_ol[];
  float* QT = sm_ol;
  float* KT = QT + 64 * LD;
  float* S = KT + 64 * LD;
  float* UP = S + 64 * LD;
  float* AT = UP + 64 * LD;
  const int bx = blockIdx.x;
  const int bh = bx >> 4, ch = bx & 15;
  const int b = bh >> 5, h = bh & 31;
  const int g = b * 8 + (h >> 2);
  const int tid = threadIdx.x, tx = tid & 15, ty = tid >> 4;
  size_t qbase = ((size_t)bh * 1024 + ch * 64) * 64;
  size_t kbase = ((size_t)g * 1024 + ch * 64) * 64;
  size_t sbase = (size_t)(g * 16 + ch) * 4096;
  for (int idx = tid; idx < 4096; idx += 256) {
    int r = idx >> 6, c = idx & 63;
    QT[c * LD + r] = g_ql[qbase + idx];
    KT[c * LD + r] = g_kl[kbase + idx];
    S[r * LD + c] = g_Spre[sbase + idx];
    UP[r * LD + c] = g_up[sbase + idx];
  }
  __syncthreads();
  float acc[4][4] = {};
#pragma unroll 8
  for (int d = 0; d < 64; d++) {
    float a[4];
#pragma unroll
    for (int i = 0; i < 4; i++) a[i] = QT[d * LD + ty * 4 + i];
    float4 b4 = *(const float4*)&KT[d * LD + tx * 4];
#pragma unroll
    for (int i = 0; i < 4; i++) {
      acc[i][0] += a[i] * b4.x; acc[i][1] += a[i] * b4.y;
      acc[i][2] += a[i] * b4.z; acc[i][3] += a[i] * b4.w;
    }
  }
#pragma unroll
  for (int i = 0; i < 4; i++)
#pragma unroll
    for (int j = 0; j < 4; j++) {
      int ii = ty * 4 + i, jj = tx * 4 + j;
      AT[ii * LD + jj] = (jj <= ii) ? acc[i][j] : 0.f;
    }
  __syncthreads();
  float o[4][4] = {};
#pragma unroll 8
  for (int d = 0; d < 64; d++) {
    float a[4];
#pragma unroll
    for (int i = 0; i < 4; i++) a[i] = QT[d * LD + ty * 4 + i];
    float4 b4 = *(const float4*)&S[d * LD + tx * 4];
#pragma unroll
    for (int i = 0; i < 4; i++) {
      o[i][0] += a[i] * b4.x; o[i][1] += a[i] * b4.y;
      o[i][2] += a[i] * b4.z; o[i][3] += a[i] * b4.w;
    }
  }
#pragma unroll 8
  for (int j0 = 0; j0 < 64; j0++) {
    float a[4];
#pragma unroll
    for (int i = 0; i < 4; i++) a[i] = AT[(ty * 4 + i) * LD + j0];
    float4 b4 = *(const float4*)&UP[j0 * LD + tx * 4];
#pragma unroll
    for (int i = 0; i < 4; i++) {
      o[i][0] += a[i] * b4.x; o[i][1] += a[i] * b4.y;
      o[i][2] += a[i] * b4.z; o[i][3] += a[i] * b4.w;
    }
  }
#pragma unroll
  for (int i = 0; i < 4; i++) {
    size_t ob = ((size_t)(b * 1024 + ch * 64 + ty * 4 + i)) * 2048 + h * 64 + tx * 4;
    *(float4*)&g_olin[ob] = make_float4(o[i][0], o[i][1], o[i][2], o[i][3]);
  }
}

// ---------------- one-pass HMMA attention, single K/V stage, fused normalize ----------------
__global__ __launch_bounds__(256) void attn_hmma(float* __restrict__ attn_out,
                                                 int write_attn) {
  extern __shared__ __align__(128) char sm[];
  const uint32_t sb = smem_u32(sm);
  const int qt = blockIdx.x, h = blockIdx.y, b = blockIdx.z;
  const int hk = h >> 2;
  const int tid = threadIdx.x, wid = tid >> 5, lane = tid & 31;
  const int wy = wid & 3, wx = wid >> 2;
  const uint32_t QH = 0, QL = 9216, ST = 18432;  // K/V stage: KH+0 KL+9216 VH+18432 VL+27648
  const uint32_t PH = 55296, PL = 64512, RED = 73728, REDT = 74240;
  float* REDp = (float*)(sm + RED);
  float* REDt = (float*)(sm + REDT);
  const size_t qbase = ((size_t)((b * 32 + h) * 1024) + (size_t)qt * 64) * 64;
  const size_t kvb = ((size_t)((b * 8 + hk) * 1024)) * 64;

  // Q loads (uncommitted; join the kt=0 commit group)
#pragma unroll
  for (int i = 0; i < 4; i++) {
    int idx = i * 256 + tid;
    int mat = idx >> 9;
    int ri = idx & 511;
    int row = ri >> 3, seg = ri & 7;
    const char* g =
        (const char*)((mat ? g_qsl : g_qsh) + qbase + (size_t)row * 64 + seg * 8);
    CPA16(sb + (mat ? QL : QH) + row * 144 + seg * 16, g);
  }

  const int r0i = wy * 16 + (lane >> 2);
  float l0 = 0.f, l1 = 0.f;
  float o[4][4] = {};
  const size_t arow0 = (size_t)(b * 32 + h) * 1024 + (size_t)qt * 64;

  for (int kt = 0; kt <= qt; kt++) {
    __syncthreads();  // prior PV reads of stage done
#pragma unroll
    for (int i = 0; i < 8; i++) {
      int idx = i * 256 + tid;
      int mat = idx >> 9;  // 0:KH 1:KL 2:VH 3:VL
      int ri = idx & 511;
      int row = ri >> 3, seg = ri & 7;
      const __nv_bfloat16* sp = (mat == 0)   ? g_ksh
                                : (mat == 1) ? g_ksl
                                : (mat == 2) ? g_vsh
                                             : g_vsl;
      const char* g =
          (const char*)(sp + kvb + (size_t)(kt * 64 + row) * 64 + seg * 8);
      CPA16(sb + ST + mat * 9216 + row * 144 + seg * 16, g);
    }
    CPCOMMIT();
    asm volatile("cp.async.wait_group 0;");
    __syncthreads();
    float s[4][4] = {};
#pragma unroll
    for (int ks = 0; ks < 4; ks++) {
      uint32_t qhf[4], qlf[4], kf[4][2], klf[4][2];
      uint32_t qoff = (wy * 16 + (lane & 15)) * 144 + ks * 32 + (lane >> 4) * 16;
      LDSM4(qhf, sb + QH + qoff);
      LDSM4(qlf, sb + QL + qoff);
#pragma unroll
      for (int np = 0; np < 2; np++) {
        int j = lane >> 3;
        uint32_t off =
            (wx * 32 + np * 16 + (j >> 1) * 8 + (lane & 7)) * 144 + ks * 32 + (j & 1) * 16;
        LDSM4(kf[2 * np], sb + ST + off);
        LDSM4(klf[2 * np], sb + ST + 9216 + off);
      }
#pragma unroll
      for (int sub = 0; sub < 4; sub++) {
        MMA16816(s[sub], qhf, kf[sub]);
        MMA16816(s[sub], qhf, klf[sub]);
        MMA16816(s[sub], qlf, kf[sub]);
      }
    }
    if (kt == qt) {
      int gr = qt * 64 + r0i;
#pragma unroll
      for (int sub = 0; sub < 4; sub++) {
        int gc = kt * 64 + wx * 32 + sub * 8 + (lane & 3) * 2;
        if (gc > gr) s[sub][0] = -1e30f;
        if (gc + 1 > gr) s[sub][1] = -1e30f;
        if (gc > gr + 8) s[sub][2] = -1e30f;
        if (gc + 1 > gr + 8) s[sub][3] = -1e30f;
      }
    }
#pragma unroll
    for (int sub = 0; sub < 4; sub++) {
      float p0 = __expf(s[sub][0]);
      float p1 = __expf(s[sub][1]);
      float p2 = __expf(s[sub][2]);
      float p3 = __expf(s[sub][3]);
      l0 += p0 + p1;
      l1 += p2 + p3;
      int cl = wx * 32 + sub * 8 + (lane & 3) * 2;
      if (write_attn) {
        int col = kt * 64 + cl;
        *(float2*)&attn_out[(arow0 + r0i) * 1024 + col] = make_float2(p0, p1);
        *(float2*)&attn_out[(arow0 + r0i + 8) * 1024 + col] = make_float2(p2, p3);
      }
      __nv_bfloat16 h0 = __float2bfloat16(p0), h1 = __float2bfloat16(p1);
      __nv_bfloat16 h2 = __float2bfloat16(p2), h3 = __float2bfloat16(p3);
      *(__nv_bfloat162*)(sm + PH + r0i * 144 + cl * 2) = __halves2bfloat162(h0, h1);
      *(__nv_bfloat162*)(sm + PH + (r0i + 8) * 144 + cl * 2) = __halves2bfloat162(h2, h3);
      *(__nv_bfloat162*)(sm + PL + r0i * 144 + cl * 2) = __halves2bfloat162(
          __float2bfloat16(p0 - __bfloat162float(h0)),
          __float2bfloat16(p1 - __bfloat162float(h1)));
      *(__nv_bfloat162*)(sm + PL + (r0i + 8) * 144 + cl * 2) = __halves2bfloat162(
          __float2bfloat16(p2 - __bfloat162float(h2)),
          __float2bfloat16(p3 - __bfloat162float(h3)));
    }
    __syncthreads();
#pragma unroll
    for (int ks = 0; ks < 4; ks++) {
      uint32_t pf[4], plf[4], vf[4][2], vlf[4][2];
      uint32_t poff = (wy * 16 + (lane & 15)) * 144 + ks * 32 + (lane >> 4) * 16;
      LDSM4(pf, sb + PH + poff);
      LDSM4(plf, sb + PL + poff);
#pragma unroll
      for (int np = 0; np < 2; np++) {
        int g2 = lane >> 3;
        uint32_t off = (ks * 16 + (g2 & 1) * 8 + (lane & 7)) * 144 +
                       (wx * 32 + np * 16) * 2 + (g2 >> 1) * 16;
        LDSM4T(vf[2 * np], sb + ST + 18432 + off);
        LDSM4T(vlf[2 * np], sb + ST + 27648 + off);
      }
#pragma unroll
      for (int sub = 0; sub < 4; sub++) {
        MMA16816(o[sub], pf, vf[sub]);
        MMA16816(o[sub], plf, vf[sub]);
        MMA16816(o[sub], pf, vlf[sub]);
      }
    }
  }

  // final l reduction (once), then invert into REDT
  l0 += __shfl_xor_sync(0xffffffffu, l0, 1);
  l0 += __shfl_xor_sync(0xffffffffu, l0, 2);
  l1 += __shfl_xor_sync(0xffffffffu, l1, 1);
  l1 += __shfl_xor_sync(0xffffffffu, l1, 2);
  if ((lane & 3) == 0) {
    REDp[r0i * 2 + wx] = l0;
    REDp[(r0i + 8) * 2 + wx] = l1;
  }
  __syncthreads();
  if (tid < 64) REDt[tid] = 1.f / (REDp[tid * 2] + REDp[tid * 2 + 1]);
  __syncthreads();
  float invl0 = REDt[r0i];
  float invl1 = REDt[r0i + 8];

  if (write_attn) {
    // zero upper-triangle tiles
    for (int kt = qt + 1; kt < 16; kt++) {
#pragma unroll
      for (int i = 0; i < 4; i++) {
        int idx = i * 256 + tid;
        int row = idx >> 4, c4 = (idx & 15) * 4;
        *(float4*)&attn_out[(arow0 + row) * 1024 + kt * 64 + c4] =
            make_float4(0.f, 0.f, 0.f, 0.f);
      }
    }
    // normalize this block's lower-triangle rows in place
    const int ncol4 = (qt + 1) * 16;
    for (int r = 0; r < 64; r++) {
      float iv = REDt[r];
      float4* rowp = (float4*)(attn_out + (arow0 + r) * 1024);
      for (int c = tid; c < ncol4; c += 256) {
        float4 v = rowp[c];
        v.x *= iv; v.y *= iv; v.z *= iv; v.w *= iv;
        rowp[c] = v;
      }
    }
  }

  // epilogue: omix = 0.5*(olin + o/l); write bf16 hi/lo directly for final GEMM
#pragma unroll
  for (int sub = 0; sub < 4; sub++) {
    int gr = qt * 64 + r0i;
    int col = wx * 32 + sub * 8 + (lane & 3) * 2;
    size_t ob = ((size_t)(b * 1024 + gr)) * 2048 + h * 64 + col;
    float2 ol = *(const float2*)&g_olin[ob];
    float m0 = 0.5f * (ol.x + o[sub][0] * invl0);
    float m1 = 0.5f * (ol.y + o[sub][1] * invl0);
    __nv_bfloat16 h0 = __float2bfloat16(m0), h1 = __float2bfloat16(m1);
    *(__nv_bfloat162*)&g_Ah[ob] = __halves2bfloat162(h0, h1);
    *(__nv_bfloat162*)&g_Al[ob] =
        __halves2bfloat162(__float2bfloat16(m0 - __bfloat162float(h0)),
                           __float2bfloat16(m1 - __bfloat162float(h1)));
    size_t ob2 = ((size_t)(b * 1024 + gr + 8)) * 2048 + h * 64 + col;
    float2 ol2 = *(const float2*)&g_olin[ob2];
    float m2 = 0.5f * (ol2.x + o[sub][2] * invl1);
    float m3 = 0.5f * (ol2.y + o[sub][3] * invl1);
    __nv_bfloat16 h2 = __float2bfloat16(m2), h3 = __float2bfloat16(m3);
    *(__nv_bfloat162*)&g_Ah[ob2] = __halves2bfloat162(h2, h3);
    *(__nv_bfloat162*)&g_Al[ob2] =
        __halves2bfloat162(__float2bfloat16(m2 - __bfloat162float(h2)),
                           __float2bfloat16(m3 - __bfloat162float(h3)));
  }
}

extern "C" void kernel_launch(void* const* d_in, const int* in_sizes, int n_in,
                              void* d_out, int out_size) {
  const float* hidden = (const float*)d_in[0];
  const float* Wq = (const float*)d_in[1];
  const float* Wk = (const float*)d_in[2];
  const float* Wv = (const float*)d_in[3];
  const float* Wo = (const float*)d_in[4];
  float* out = (float*)d_out;
  float* attn_out = out + 4194304;
  int write_attn = (out_size >= 71303168) ? 1 : 0;

  __nv_bfloat16 *gAh, *gAl, *gWqh, *gWql, *gWkh, *gWkl, *gWvh, *gWvl, *gWoh, *gWol;
  cudaGetSymbolAddress((void**)&gAh, g_Ah);
  cudaGetSymbolAddress((void**)&gAl, g_Al);
  cudaGetSymbolAddress((void**)&gWqh, g_Wqh);
  cudaGetSymbolAddress((void**)&gWql, g_Wql);
  cudaGetSymbolAddress((void**)&gWkh, g_Wkh);
  cudaGetSymbolAddress((void**)&gWkl, g_Wkl);
  cudaGetSymbolAddress((void**)&gWvh, g_Wvh);
  cudaGetSymbolAddress((void**)&gWvl, g_Wvl);
  cudaGetSymbolAddress((void**)&gWoh, g_Woh);
  cudaGetSymbolAddress((void**)&gWol, g_Wol);

  static const int smem_uw = (3 * 64 * LD + 64 * 136) * 4;
  static const int smem_ol = 5 * 64 * LD * 4;
  static const int smem_g = 2 * 40960;
  static const int smem_at = 74752;
  cudaFuncSetAttribute(uw_kernel, cudaFuncAttributeMaxDynamicSharedMemorySize, smem_uw);
  cudaFuncSetAttribute(olin_kernel, cudaFuncAttributeMaxDynamicSharedMemorySize, smem_ol);
  cudaFuncSetAttribute(hmma_gemm, cudaFuncAttributeMaxDynamicSharedMemorySize, smem_g);
  cudaFuncSetAttribute(hmma_gemm_qkv, cudaFuncAttributeMaxDynamicSharedMemorySize, smem_g);
  cudaFuncSetAttribute(attn_hmma, cudaFuncAttributeMaxDynamicSharedMemorySize, smem_at);

  split_kernel<<<4096, 256>>>(hidden, gAh, gAl, 1048576);
  splitT_kernel<<<dim3(64, 64), 256>>>(Wq, gWqh, gWql, 2048, 2048);
  splitT_kernel<<<dim3(16, 64), 256>>>(Wk, gWkh, gWkl, 2048, 512);
  splitT_kernel<<<dim3(16, 64), 256>>>(Wv, gWvh, gWvl, 2048, 512);
  splitT_kernel<<<dim3(64, 64), 256>>>(Wo, gWoh, gWol, 2048, 2048);

  hmma_gemm_qkv<<<dim3(24, 16), 256, smem_g>>>();

  prep_kernel<<<10240, 256>>>();
  uw_kernel<<<256, 256, smem_uw>>>();
  recur_kernel<<<64, 256>>>();
  olin_kernel<<<1024, 256, smem_ol>>>();
  attn_hmma<<<dim3(16, 32, 2), 256, smem_at>>>(attn_out, write_attn);

  hmma_gemm<<<dim3(16, 16), 256, smem_g>>>(gAh, gAl, gWoh, gWol, out, 2048, 2048);
}